// round 16
// baseline (speedup 1.0000x reference)
#include <cuda_runtime.h>
#include <stdint.h>

#define NB 32
#define CI 32
#define CO 32
#define HH 128
#define WW 128

// Scratch (static __device__ arrays: allocation-free, graph-safe)
__device__ signed char g_act_nhwc[(size_t)NB * HH * WW * CI];  // 16 MB NHWC int8
__device__ int g_max;
__device__ unsigned g_wpack[CO * 9 * 8];                       // packed weights

// NCHW int32 -> NHWC int8. One thread = one 16B output chunk (pixel, ci-half).
// Reads: 64B-coalesced per ci; writes: fully contiguous STG.128.
// Block 0 also packs weights + resets g_max.
__global__ void k_transpose(const int* __restrict__ act, const int* __restrict__ w) {
    int idx = blockIdx.x * blockDim.x + threadIdx.x;  // NB*HH*WW*2 threads
    int half = idx & 1;
    int p = idx >> 1;              // pixel: n*16384 + y*128 + x
    int x = p & (WW - 1);
    int y = (p >> 7) & (HH - 1);
    int n = p >> 14;

    const int* src = act + ((size_t)(n * CI + half * 16) * HH + y) * WW + x;
    unsigned vv[4];
#pragma unroll
    for (int j = 0; j < 4; j++) {
        unsigned v = 0;
#pragma unroll
        for (int bb = 0; bb < 4; bb++) {
            unsigned c = (unsigned)src[(size_t)(j * 4 + bb) * HH * WW] & 0xFFu;
            v |= c << (8 * bb);
        }
        vv[j] = v;
    }
    *(uint4*)(g_act_nhwc + ((size_t)p << 5) + (half << 4)) =
        make_uint4(vv[0], vv[1], vv[2], vv[3]);

    if (blockIdx.x == 0) {
        if (threadIdx.x == 0) g_max = 0;
        for (int i = threadIdx.x; i < CO * 9 * 8; i += blockDim.x) {
            int ciw = i & 7;
            int t = (i >> 3) % 9;
            int co = i / 72;
            int kh = t / 3, kw = t - kh * 3;
            unsigned v = 0;
#pragma unroll
            for (int j = 0; j < 4; j++) {
                int ci = ciw * 4 + j;
                unsigned b = (unsigned)(w[((co * CI + ci) * 3 + kh) * 3 + kw]) & 0xFFu;
                v |= b << (8 * j);
            }
            g_wpack[i] = v;
        }
    }
}

__device__ __forceinline__ void mma_s8(int d[4], const unsigned a[4],
                                       unsigned b0, unsigned b1) {
    asm volatile(
        "mma.sync.aligned.m16n8k32.row.col.s32.s8.s8.s32 "
        "{%0,%1,%2,%3}, {%4,%5,%6,%7}, {%8,%9}, {%0,%1,%2,%3};\n"
        : "+r"(d[0]), "+r"(d[1]), "+r"(d[2]), "+r"(d[3])
        : "r"(a[0]), "r"(a[1]), "r"(a[2]), "r"(a[3]), "r"(b0), "r"(b1));
}

__device__ __forceinline__ void ldm4(unsigned r[4], unsigned saddr) {
    asm volatile(
        "ldmatrix.sync.aligned.m8n8.x4.shared.b16 {%0,%1,%2,%3}, [%4];\n"
        : "=r"(r[0]), "=r"(r[1]), "=r"(r[2]), "=r"(r[3])
        : "r"(saddr));
}

// swizzle: XOR bit4 with bit7 of the byte offset
__device__ __forceinline__ unsigned swz(unsigned off) {
    return off ^ ((off >> 3) & 16);
}

// Bit-exact replica of psto_shift + act_calc select paths.
__device__ __forceinline__ float quantize_one(int v, int shift, int eff) {
    if (shift < 1) return (float)(signed char)v;  // truncating int8 cast
    int rt = v >> eff;                            // floor division by 2^eff
    int prob = v & ((1 << eff) - 1);              // non-negative remainder
    int h = eff >> 1;
    int qp = prob >> h;
    int pr = prob & ((1 << h) - 1);
    if (eff & 1) pr <<= 1;
    int sgn = (v >> 31) | 1;                      // v==0 never decrements (prob=0)
    int r = rt + ((qp <= pr) ? 0 : sgn);
    r = r < -127 ? -127 : (r > 127 ? 127 : r);
    return (float)r;
}

// Implicit-GEMM conv via IMMA + ldmatrix. Block = 4 output rows (n fixed).
// 8 warps: warp w -> rows r0=(w>>2)*2..+1, x-segment (w&3)*32.
// Warp tile = 2 rows x 32 px x 32 co, A-row reuse across the 2 rows.
// MODE 0: |max| only. MODE 1: quantize + smem-staged 128B-coalesced stores.
template <int MODE>
__global__ void __launch_bounds__(256) k_conv(const int* __restrict__ expin,
                                              const int* __restrict__ wexp,
                                              float* __restrict__ out,
                                              int out_size) {
    __shared__ __align__(128) signed char s_act[6 * 130 * 32];  // swizzled; reused
    __shared__ __align__(128) signed char s_w[9 * 32 * 32];     // swizzled

    int tid = threadIdx.x;
    int b = blockIdx.x;
    int n = b >> 5;
    int y0 = (b & 31) << 2;

    // zero act tile (halo rows/cols)
    uint4* sa4 = (uint4*)s_act;
#pragma unroll
    for (int i = tid; i < 6 * 130 * 32 / 16; i += 256) sa4[i] = make_uint4(0, 0, 0, 0);
    // weights: (co,t,8 words) -> s_w[t][co] 32B rows, swizzled, 16B at a time
    for (int i = tid; i < 9 * 32 * 2; i += 256) {
        int h = i & 1;
        int co = (i >> 1) & 31;
        int t = i >> 6;
        unsigned off = ((unsigned)(t * 32 + co) << 5) + (h << 4);
        *(uint4*)(s_w + swz(off)) = ((const uint4*)g_wpack)[(co * 9 + t) * 2 + h];
    }
    __syncthreads();

    // fill interior: 6 rows x 128 px x 32B, swizzled
    {
        int px = tid >> 1;
        int half = (tid & 1) << 4;
#pragma unroll
        for (int r = 0; r < 6; r++) {
            int iy = y0 + r - 1;
            if ((unsigned)iy < HH) {
                const uint4* src = (const uint4*)(g_act_nhwc +
                    ((((size_t)n * HH + iy) * WW + px) << 5) + half);
                unsigned off = ((unsigned)((r * 130 + px + 1) << 5)) + half;
                *(uint4*)(s_act + swz(off)) = *src;
            }
        }
    }
    __syncthreads();

    int lane = tid & 31;
    int wid = tid >> 5;
    int r0 = (wid >> 2) << 1;
    int xbase = (wid & 3) << 5;

    unsigned actS = (unsigned)__cvta_generic_to_shared(s_act);
    unsigned wS = (unsigned)__cvta_generic_to_shared(s_w);

    // ldmatrix lane-dependent base offsets
    unsigned alane = ((unsigned)(lane & 15) << 5) + ((lane >> 4) << 4);
    unsigned bbase = ((unsigned)(((lane >> 4) << 3) + (lane & 7)) << 5) +
                     (((lane >> 3) & 1) << 4);

    int acc[2][2][4][4];  // [row][m][ns][k]
#pragma unroll
    for (int rr = 0; rr < 2; rr++)
#pragma unroll
        for (int m = 0; m < 2; m++)
#pragma unroll
            for (int ns = 0; ns < 4; ns++)
#pragma unroll
                for (int k = 0; k < 4; k++) acc[rr][m][ns][k] = 0;

#pragma unroll
    for (int kx = 0; kx < 3; kx++) {
        // cache B fragments for ky = 0,1,2 at this kx (taps t = ky*3+kx)
        unsigned bf[3][2][4];
#pragma unroll
        for (int ky = 0; ky < 3; ky++) {
            unsigned bo = bbase + ((unsigned)(ky * 3 + kx) << 10);
            ldm4(bf[ky][0], wS + swz(bo));
            ldm4(bf[ky][1], wS + swz(bo + 512));
        }
        // 4 distinct A rows; each feeds all valid (rr, ky = ra - rr)
#pragma unroll
        for (int ra = 0; ra < 4; ra++) {
            unsigned af[2][4];
            unsigned ao = alane +
                ((unsigned)((r0 + ra) * 130 + xbase + kx) << 5);
            ldm4(af[0], actS + swz(ao));
            ldm4(af[1], actS + swz(ao + 512));
#pragma unroll
            for (int rr = 0; rr < 2; rr++) {
                int ky = ra - rr;
                if (ky >= 0 && ky < 3) {
#pragma unroll
                    for (int m = 0; m < 2; m++) {
                        mma_s8(acc[rr][m][0], af[m], bf[ky][0][0], bf[ky][0][1]);
                        mma_s8(acc[rr][m][1], af[m], bf[ky][0][2], bf[ky][0][3]);
                        mma_s8(acc[rr][m][2], af[m], bf[ky][1][0], bf[ky][1][1]);
                        mma_s8(acc[rr][m][3], af[m], bf[ky][1][2], bf[ky][1][3]);
                    }
                }
            }
        }
    }

    int g = lane >> 2;
    int tig = lane & 3;

    if (MODE == 0) {
        int mloc = 0;
#pragma unroll
        for (int rr = 0; rr < 2; rr++)
#pragma unroll
            for (int m = 0; m < 2; m++)
#pragma unroll
                for (int ns = 0; ns < 4; ns++)
#pragma unroll
                    for (int k = 0; k < 4; k++) {
                        int a = acc[rr][m][ns][k];
                        mloc = max(mloc, a < 0 ? -a : a);
                    }
        mloc = __reduce_max_sync(0xffffffffu, mloc);
        if (lane == 0) atomicMax(&g_max, mloc);
    } else {
        int gmax = g_max;
        int bw = gmax ? (32 - __clz(gmax - 1)) : 0;  // exact ceil(log2)
        int shift = bw - 7;
        int eff = shift > 1 ? shift : 2;

        // Staged epilogue: 4 co-groups of 8. Stage [8 co][4 y][128 x] floats
        // (16 KB) in s_act, then emit fully coalesced float4 stores.
        float* s_out = (float*)s_act;
        __syncthreads();  // all ldmatrix reads of s_act complete
#pragma unroll 1
        for (int cg = 0; cg < 4; cg++) {
#pragma unroll
            for (int rr = 0; rr < 2; rr++)
#pragma unroll
                for (int m = 0; m < 2; m++)
#pragma unroll
                    for (int k = 0; k < 4; k++) {
                        int co_l = tig * 2 + (k & 1);
                        int y_l = r0 + rr;
                        int x = xbase + m * 16 + g + ((k >> 1) << 3);
                        s_out[(co_l * 4 + y_l) * 128 + x] =
                            quantize_one(acc[rr][m][cg][k], shift, eff);
                    }
            __syncthreads();
            // 4096 floats = 1024 float4; 256 threads x 4; contiguous per (co,y)
#pragma unroll
            for (int r = 0; r < 4; r++) {
                int iu = tid + (r << 8);
                int x4 = iu & 31;
                int y_l = (iu >> 5) & 3;
                int co_l = iu >> 7;
                float4 v = ((const float4*)s_out)[iu];
                *(float4*)(out +
                    (((size_t)(n * 32 + (cg << 3) + co_l) * 128 + y0 + y_l) << 7) +
                    (x4 << 2)) = v;
            }
            __syncthreads();
        }

        if (b == 0 && tid == 0) {
            int inc = shift > 1 ? shift : (shift == 1 ? 2 : 0);
            int e = expin[0] + wexp[0] + inc;
            out[out_size - 1] = (float)(signed char)e;
        }
    }
}

extern "C" void kernel_launch(void* const* d_in, const int* in_sizes, int n_in,
                              void* d_out, int out_size) {
    const int* act = (const int*)d_in[0];
    const int* expin = (const int*)d_in[1];
    const int* w = (const int*)d_in[2];
    const int* wexp = (const int*)d_in[3];
    float* out = (float*)d_out;

    k_transpose<<<(NB * HH * WW * 2) / 256, 256>>>(act, w);
    k_conv<0><<<NB * 32, 256>>>(expin, wexp, out, out_size);  // max pass
    k_conv<1><<<NB * 32, 256>>>(expin, wexp, out, out_size);  // quantize pass
}

// round 17
// speedup vs baseline: 1.6356x; 1.6356x over previous
#include <cuda_runtime.h>
#include <stdint.h>

#define NB 32
#define CI 32
#define CO 32
#define HH 128
#define WW 128
#define GRIDC 296            // persistent conv blocks (~2/SM)
#define NTILE 2048           // 2-row tiles: 32 images x 64
#define TILEB (4 * 130 * 32) // 16640 B per act buffer (128-aligned)

// Scratch (static __device__ arrays: allocation-free, graph-safe)
__device__ signed char g_act_nhwc[(size_t)NB * HH * WW * CI];  // 16 MB NHWC int8
__device__ int g_max;
__device__ unsigned g_wpack[CO * 9 * 8];                       // packed weights

// NCHW int32 -> NHWC int8. One thread = one 16B output chunk (pixel, ci-half).
// Block 0 also packs weights + resets g_max.
__global__ void k_transpose(const int* __restrict__ act, const int* __restrict__ w) {
    int idx = blockIdx.x * blockDim.x + threadIdx.x;  // NB*HH*WW*2 threads
    int half = idx & 1;
    int p = idx >> 1;
    int x = p & (WW - 1);
    int y = (p >> 7) & (HH - 1);
    int n = p >> 14;

    const int* src = act + ((size_t)(n * CI + half * 16) * HH + y) * WW + x;
    unsigned vv[4];
#pragma unroll
    for (int j = 0; j < 4; j++) {
        unsigned v = 0;
#pragma unroll
        for (int bb = 0; bb < 4; bb++) {
            unsigned c = (unsigned)src[(size_t)(j * 4 + bb) * HH * WW] & 0xFFu;
            v |= c << (8 * bb);
        }
        vv[j] = v;
    }
    *(uint4*)(g_act_nhwc + ((size_t)p << 5) + (half << 4)) =
        make_uint4(vv[0], vv[1], vv[2], vv[3]);

    if (blockIdx.x == 0) {
        if (threadIdx.x == 0) g_max = 0;
        for (int i = threadIdx.x; i < CO * 9 * 8; i += blockDim.x) {
            int ciw = i & 7;
            int t = (i >> 3) % 9;
            int co = i / 72;
            int kh = t / 3, kw = t - kh * 3;
            unsigned v = 0;
#pragma unroll
            for (int j = 0; j < 4; j++) {
                int ci = ciw * 4 + j;
                unsigned b = (unsigned)(w[((co * CI + ci) * 3 + kh) * 3 + kw]) & 0xFFu;
                v |= b << (8 * j);
            }
            g_wpack[i] = v;
        }
    }
}

__device__ __forceinline__ void mma_s8(int d[4], const unsigned a[4],
                                       unsigned b0, unsigned b1) {
    asm volatile(
        "mma.sync.aligned.m16n8k32.row.col.s32.s8.s8.s32 "
        "{%0,%1,%2,%3}, {%4,%5,%6,%7}, {%8,%9}, {%0,%1,%2,%3};\n"
        : "+r"(d[0]), "+r"(d[1]), "+r"(d[2]), "+r"(d[3])
        : "r"(a[0]), "r"(a[1]), "r"(a[2]), "r"(a[3]), "r"(b0), "r"(b1));
}

__device__ __forceinline__ void ldm4(unsigned r[4], unsigned saddr) {
    asm volatile(
        "ldmatrix.sync.aligned.m8n8.x4.shared.b16 {%0,%1,%2,%3}, [%4];\n"
        : "=r"(r[0]), "=r"(r[1]), "=r"(r[2]), "=r"(r[3])
        : "r"(saddr));
}

__device__ __forceinline__ void cpa16(unsigned dst, const void* src) {
    asm volatile("cp.async.cg.shared.global [%0], [%1], 16;\n" ::"r"(dst),
                 "l"(src));
}

// swizzle: XOR bit4 with bit7 of the byte offset
__device__ __forceinline__ unsigned swz(unsigned off) {
    return off ^ ((off >> 3) & 16);
}

// Bit-exact replica of psto_shift + act_calc select paths.
__device__ __forceinline__ float quantize_one(int v, int shift, int eff) {
    if (shift < 1) return (float)(signed char)v;  // truncating int8 cast
    int rt = v >> eff;                            // floor division by 2^eff
    int prob = v & ((1 << eff) - 1);              // non-negative remainder
    int h = eff >> 1;
    int qp = prob >> h;
    int pr = prob & ((1 << h) - 1);
    if (eff & 1) pr <<= 1;
    int sgn = (v >> 31) | 1;                      // v==0 never decrements (prob=0)
    int r = rt + ((qp <= pr) ? 0 : sgn);
    r = r < -127 ? -127 : (r > 127 ? 127 : r);
    return (float)r;
}

// Issue the cp.async fill for one 2-row tile into buffer `buf` (sync STS zeros
// for out-of-range rows). 4 input rows x 128 px x 32B; 4 x 16B per thread.
__device__ __forceinline__ void fill_tile(signed char* buf, unsigned bufS,
                                          int tile, int tid) {
    int n = tile >> 6;
    int y0 = (tile & 63) << 1;
    int px = tid >> 1;
    int half = (tid & 1) << 4;
#pragma unroll
    for (int r = 0; r < 4; r++) {
        int iy = y0 + r - 1;
        unsigned off = swz(((unsigned)((r * 130 + px + 1) << 5)) + half);
        if ((unsigned)iy < HH) {
            cpa16(bufS + off, g_act_nhwc +
                ((((size_t)n * HH + iy) * WW + px) << 5) + half);
        } else {
            *(uint4*)(buf + off) = make_uint4(0, 0, 0, 0);
        }
    }
    asm volatile("cp.async.commit_group;\n");
}

// Persistent implicit-GEMM conv. Each block loops tiles (stride GRIDC) with
// cp.async double-buffered fills. Tile = 2 output rows; 8 warps: warp w ->
// row (w>>2), x-seg (w&3)*32; warp tile = 32 px x 32 co.
// MODE 0: global |max| only. MODE 1: quantize + float store.
template <int MODE>
__global__ void __launch_bounds__(256) k_conv(const int* __restrict__ expin,
                                              const int* __restrict__ wexp,
                                              float* __restrict__ out,
                                              int out_size) {
    __shared__ __align__(128) signed char s_act[2 * TILEB];  // double buffer
    __shared__ __align__(128) signed char s_w[9 * 32 * 32];  // swizzled weights

    int tid = threadIdx.x;
    int bl = blockIdx.x;

    // weights -> smem (swizzled)
    for (int i = tid; i < 9 * 32 * 2; i += 256) {
        int h = i & 1;
        int co = (i >> 1) & 31;
        int t = i >> 6;
        unsigned off = ((unsigned)(t * 32 + co) << 5) + (h << 4);
        *(uint4*)(s_w + swz(off)) = ((const uint4*)g_wpack)[(co * 9 + t) * 2 + h];
    }
    // zero halo columns (cols 0,129) in BOTH buffers; fills never touch them
    if (tid < 32) {
        int pbuf = tid >> 4;
        int r = tid & 3;
        int col = ((tid >> 2) & 1) ? 129 : 0;
        unsigned half = ((unsigned)(tid >> 3) & 1) << 4;
        unsigned off = ((unsigned)(r * 130 + col) << 5) + half;
        *(uint4*)(s_act + pbuf * TILEB + swz(off)) = make_uint4(0, 0, 0, 0);
    }

    unsigned actS0 = (unsigned)__cvta_generic_to_shared(s_act);
    unsigned wS = (unsigned)__cvta_generic_to_shared(s_w);

    int lane = tid & 31;
    int wid = tid >> 5;
    int row = wid >> 2;
    int xbase = (wid & 3) << 5;
    unsigned abase = ((unsigned)(row * 130 + xbase + (lane & 15)) << 5) +
                     ((lane >> 4) << 4);
    unsigned bbase = ((unsigned)(((lane >> 4) << 3) + (lane & 7)) << 5) +
                     (((lane >> 3) & 1) << 4);
    int g = lane >> 2;
    int tig = lane & 3;

    int shift = 0, eff = 0;
    if (MODE == 1) {
        int gmax = g_max;
        int bw = gmax ? (32 - __clz(gmax - 1)) : 0;  // exact ceil(log2)
        shift = bw - 7;
        eff = shift > 1 ? shift : 2;
        if (bl == 0 && tid == 0) {
            int inc = shift > 1 ? shift : (shift == 1 ? 2 : 0);
            int e = expin[0] + wexp[0] + inc;
            out[out_size - 1] = (float)(signed char)e;
        }
    }

    int mret = 0;
    int tile = bl;
    int p = 0;
    fill_tile(s_act, actS0, tile, tid);  // prologue fill into buf 0

#pragma unroll 1
    while (tile < NTILE) {
        asm volatile("cp.async.wait_group 0;\n");
        __syncthreads();  // current buffer ready for ALL threads; other buffer
                          // fully consumed (all threads passed previous compute)
        int nt = tile + GRIDC;
        if (nt < NTILE)
            fill_tile(s_act + (p ^ 1) * TILEB, actS0 + (p ^ 1) * TILEB, nt, tid);
        asm volatile("cp.async.commit_group;\n");  // harmless if empty

        unsigned actS = actS0 + p * TILEB;
        int n = tile >> 6;
        int y0 = (tile & 63) << 1;

        int acc[2][4][4];
#pragma unroll
        for (int m = 0; m < 2; m++)
#pragma unroll
            for (int ns = 0; ns < 4; ns++)
#pragma unroll
                for (int k = 0; k < 4; k++) acc[m][ns][k] = 0;

#pragma unroll
        for (int t = 0; t < 9; t++) {
            const int ky = t / 3, kx = t - 3 * (t / 3);
            unsigned af[2][4], bf[2][4];
            unsigned ao = abase + ((unsigned)(ky * 130 + kx) << 5);
            ldm4(af[0], actS + swz(ao));
            ldm4(af[1], actS + swz(ao + 512));
            unsigned bo = bbase + ((unsigned)t << 10);
            ldm4(bf[0], wS + swz(bo));
            ldm4(bf[1], wS + swz(bo + 512));
#pragma unroll
            for (int m = 0; m < 2; m++) {
                mma_s8(acc[m][0], af[m], bf[0][0], bf[0][1]);
                mma_s8(acc[m][1], af[m], bf[0][2], bf[0][3]);
                mma_s8(acc[m][2], af[m], bf[1][0], bf[1][1]);
                mma_s8(acc[m][3], af[m], bf[1][2], bf[1][3]);
            }
        }

        if (MODE == 0) {
#pragma unroll
            for (int m = 0; m < 2; m++)
#pragma unroll
                for (int ns = 0; ns < 4; ns++)
#pragma unroll
                    for (int k = 0; k < 4; k++) {
                        int a = acc[m][ns][k];
                        mret = max(mret, a < 0 ? -a : a);
                    }
        } else {
            int y = y0 + row;
#pragma unroll
            for (int m = 0; m < 2; m++)
#pragma unroll
                for (int ns = 0; ns < 4; ns++) {
                    int x0p = xbase + m * 16 + g;
                    int co0 = ns * 8 + tig * 2;
                    float* base0 = out + (((n * 32 + co0) * 128 + y) * 128);
                    float* base1 = base0 + 128 * 128;
                    base0[x0p] = quantize_one(acc[m][ns][0], shift, eff);
                    base1[x0p] = quantize_one(acc[m][ns][1], shift, eff);
                    base0[x0p + 8] = quantize_one(acc[m][ns][2], shift, eff);
                    base1[x0p + 8] = quantize_one(acc[m][ns][3], shift, eff);
                }
        }

        tile = nt;
        p ^= 1;
    }

    if (MODE == 0) {
        mret = __reduce_max_sync(0xffffffffu, mret);
        if (lane == 0) atomicMax(&g_max, mret);
    }
}

extern "C" void kernel_launch(void* const* d_in, const int* in_sizes, int n_in,
                              void* d_out, int out_size) {
    const int* act = (const int*)d_in[0];
    const int* expin = (const int*)d_in[1];
    const int* w = (const int*)d_in[2];
    const int* wexp = (const int*)d_in[3];
    float* out = (float*)d_out;

    k_transpose<<<(NB * HH * WW * 2) / 256, 256>>>(act, w);
    k_conv<0><<<GRIDC, 256>>>(expin, wexp, out, out_size);  // max pass
    k_conv<1><<<GRIDC, 256>>>(expin, wexp, out, out_size);  // quantize pass
}